// round 4
// baseline (speedup 1.0000x reference)
#include <cuda_runtime.h>
#include <cstdint>

// x: [32, 512, 56, 56] fp32. Chunk = 8 batches = 4096 slices = 51.4 MB.
// Per chunk: reduce (DRAM read, lands in L2) -> scale (L2 read, DRAM write).

#define C         512
#define CR        32
#define SPATIAL4  784                  // 56*56/4 float4 per (b,c) slice
#define CHUNK_B   8
#define NCHUNK    4
#define CHUNK_SLICES (CHUNK_B * C)     // 4096

__device__ float d_sq[32 * C];

// ---------------------------------------------------------------------------
// Reduce: one block per slice of the chunk. Default-cached loads so the
// chunk stays L2-resident for the scale pass.
// ---------------------------------------------------------------------------
__global__ __launch_bounds__(128) void se_reduce_chunk(
    const float* __restrict__ x, int slice0)
{
    const int s = slice0 + blockIdx.x;
    const float4* __restrict__ p =
        reinterpret_cast<const float4*>(x) + (size_t)s * SPATIAL4;

    float acc = 0.0f;
    #pragma unroll
    for (int i = threadIdx.x; i < SPATIAL4; i += 128) {
        float4 v = p[i];
        acc += (v.x + v.y) + (v.z + v.w);
    }

    #pragma unroll
    for (int off = 16; off > 0; off >>= 1)
        acc += __shfl_down_sync(0xFFFFFFFFu, acc, off);

    __shared__ float ws[4];
    const int lane = threadIdx.x & 31;
    const int wid  = threadIdx.x >> 5;
    if (lane == 0) ws[wid] = acc;
    __syncthreads();

    if (threadIdx.x == 0)
        d_sq[s] = (ws[0] + ws[1] + ws[2] + ws[3]) * (1.0f / 3136.0f);
}

// ---------------------------------------------------------------------------
// Scale: 512 threads, 16 warps, one slice per warp. Preamble computes the
// chunk's 8x32 hidden units in smem (redundant per block, ~cheap vs memory).
// x reads: __ldcs (L2 hit, then dead). out writes: __stcs (evict-first).
// ---------------------------------------------------------------------------
__global__ __launch_bounds__(512) void se_scale_chunk(
    const float* __restrict__ x,
    const float* __restrict__ w1,
    const float* __restrict__ b1,
    const float* __restrict__ w2,
    const float* __restrict__ b2,
    float* __restrict__ out,
    int batch0)
{
    const int tid  = threadIdx.x;
    const int lane = tid & 31;
    const int wid  = tid >> 5;

    __shared__ float hid[CHUNK_B * CR];   // 256

    // --- excitation FC1: threads 0..255 each compute one hidden unit ---
    if (tid < CHUNK_B * CR) {
        const int bl = tid >> 5;           // local batch
        const int j  = tid & 31;           // hidden unit
        const float4* __restrict__ sq4 =
            reinterpret_cast<const float4*>(d_sq + (size_t)(batch0 + bl) * C);
        const float4* __restrict__ w14 =
            reinterpret_cast<const float4*>(w1 + (size_t)j * C);
        float a0 = 0.f, a1 = 0.f, a2 = 0.f, a3 = 0.f;
        #pragma unroll 4
        for (int i = 0; i < C / 4; ++i) {
            float4 sv = sq4[i];
            float4 wv = w14[i];
            a0 = fmaf(sv.x, wv.x, a0);
            a1 = fmaf(sv.y, wv.y, a1);
            a2 = fmaf(sv.z, wv.z, a2);
            a3 = fmaf(sv.w, wv.w, a3);
        }
        hid[tid] = fmaxf((a0 + a1) + (a2 + a3) + __ldg(&b1[j]), 0.0f);
    }
    __syncthreads();

    // --- this warp's slice ---
    const int s  = blockIdx.x * 16 + wid;        // 0..4095 within chunk
    const int bl = s >> 9;                       // local batch
    const int ch = s & (C - 1);                  // channel

    // excitation FC2 + sigmoid (every lane computes the same e)
    float acc = __ldg(&b2[ch]);
    const float* __restrict__ hb  = hid + bl * CR;
    const float4* __restrict__ w24 =
        reinterpret_cast<const float4*>(w2 + (size_t)ch * CR);
    #pragma unroll
    for (int i = 0; i < CR / 4; ++i) {
        float4 wv = w24[i];
        acc = fmaf(hb[4 * i + 0], wv.x, acc);
        acc = fmaf(hb[4 * i + 1], wv.y, acc);
        acc = fmaf(hb[4 * i + 2], wv.z, acc);
        acc = fmaf(hb[4 * i + 3], wv.w, acc);
    }
    const float e = 1.0f / (1.0f + __expf(-acc));

    const size_t gslice = (size_t)batch0 * C + s;
    const float4* __restrict__ p =
        reinterpret_cast<const float4*>(x) + gslice * SPATIAL4;
    float4* __restrict__ q =
        reinterpret_cast<float4*>(out) + gslice * SPATIAL4;

    // 784 float4 = 6 groups of (4 loads x 32 lanes) + 16-lane tail
    #pragma unroll
    for (int g = 0; g < 6; ++g) {
        float4 v[4];
        #pragma unroll
        for (int i = 0; i < 4; ++i)
            v[i] = __ldcs(p + lane + 32 * (g * 4 + i));
        #pragma unroll
        for (int i = 0; i < 4; ++i) {
            float4 r = v[i];
            r.x *= e; r.y *= e; r.z *= e; r.w *= e;
            __stcs(q + lane + 32 * (g * 4 + i), r);
        }
    }
    if (lane < 16) {
        float4 v = __ldcs(p + 768 + lane);
        v.x *= e; v.y *= e; v.z *= e; v.w *= e;
        __stcs(q + 768 + lane, v);
    }
}

// ---------------------------------------------------------------------------
extern "C" void kernel_launch(void* const* d_in, const int* in_sizes, int n_in,
                              void* d_out, int out_size) {
    const float* x  = (const float*)d_in[0];
    const float* w1 = (const float*)d_in[1];
    const float* b1 = (const float*)d_in[2];
    const float* w2 = (const float*)d_in[3];
    const float* b2 = (const float*)d_in[4];
    float* out = (float*)d_out;

    for (int ck = 0; ck < NCHUNK; ++ck) {
        const int batch0 = ck * CHUNK_B;
        const int slice0 = batch0 * C;
        se_reduce_chunk<<<CHUNK_SLICES, 128>>>(x, slice0);
        se_scale_chunk<<<CHUNK_SLICES / 16, 512>>>(x, w1, b1, w2, b2, out,
                                                   batch0);
    }
}

// round 5
// speedup vs baseline: 1.8326x; 1.8326x over previous
#include <cuda_runtime.h>
#include <cstdint>

// x: [32, 512, 56, 56] fp32. Chunk = 8 batches = 4096 slices = 51.4 MB (fits L2).
// Per chunk: reduce (DRAM read -> L2) -> excite (tiny) -> scale (L2 read, DRAM write).
// DRAM total: 205 MB read + 205 MB write = 410 MB vs 616 MB unchunked.

#define C         512
#define CR        32
#define SPATIAL4  784                  // 56*56/4 float4 per (b,c) slice
#define CHUNK_B   8
#define NCHUNK    4
#define CHUNK_SLICES (CHUNK_B * C)     // 4096
#define CHUNK_F4  (CHUNK_SLICES * SPATIAL4)   // 3,211,264

__device__ float d_sq[32 * C];
__device__ float d_e[32 * C];

// ---------------------------------------------------------------------------
// Reduce: one block per slice. Default-cached loads -> chunk lands in L2.
// (Identical shape to the R1 kernel measured at 6.28 TB/s.)
// ---------------------------------------------------------------------------
__global__ __launch_bounds__(128) void se_reduce_chunk(
    const float* __restrict__ x, int slice0)
{
    const int s = slice0 + blockIdx.x;
    const float4* __restrict__ p =
        reinterpret_cast<const float4*>(x) + (size_t)s * SPATIAL4;

    float acc = 0.0f;
    #pragma unroll
    for (int i = threadIdx.x; i < SPATIAL4; i += 128) {
        float4 v = p[i];
        acc += (v.x + v.y) + (v.z + v.w);
    }

    #pragma unroll
    for (int off = 16; off > 0; off >>= 1)
        acc += __shfl_down_sync(0xFFFFFFFFu, acc, off);

    __shared__ float ws[4];
    const int lane = threadIdx.x & 31;
    const int wid  = threadIdx.x >> 5;
    if (lane == 0) ws[wid] = acc;
    __syncthreads();

    if (threadIdx.x == 0)
        d_sq[s] = (ws[0] + ws[1] + ws[2] + ws[3]) * (1.0f / 3136.0f);
}

// ---------------------------------------------------------------------------
// Excite: one block per batch of the chunk (8 blocks, 1024 threads).
// Warp j: hid[j] via 16 FMAs/lane + shuffle reduce. Then threads 0..511
// compute e[c] = sigmoid(hid . w2[c] + b2[c]).
// ---------------------------------------------------------------------------
__global__ __launch_bounds__(1024) void se_excite_chunk(
    const float* __restrict__ w1,
    const float* __restrict__ b1,
    const float* __restrict__ w2,
    const float* __restrict__ b2,
    int batch0)
{
    const int b    = batch0 + blockIdx.x;
    const int t    = threadIdx.x;
    const int wid  = t >> 5;
    const int lane = t & 31;

    __shared__ float sq[C];
    __shared__ float hid[CR];

    if (t < C) sq[t] = d_sq[b * C + t];
    __syncthreads();

    {
        const float* __restrict__ wrow = w1 + wid * C;
        float acc = 0.0f;
        #pragma unroll
        for (int k = 0; k < 16; ++k) {
            int idx = lane + 32 * k;
            acc = fmaf(sq[idx], wrow[idx], acc);
        }
        #pragma unroll
        for (int off = 16; off > 0; off >>= 1)
            acc += __shfl_down_sync(0xFFFFFFFFu, acc, off);
        if (lane == 0) hid[wid] = fmaxf(acc + b1[wid], 0.0f);
    }
    __syncthreads();

    if (t < C) {
        float acc = b2[t];
        const float* __restrict__ w2row = w2 + t * CR;
        #pragma unroll
        for (int j = 0; j < CR; ++j)
            acc = fmaf(hid[j], w2row[j], acc);
        d_e[b * C + t] = 1.0f / (1.0f + __expf(-acc));
    }
}

// ---------------------------------------------------------------------------
// Scale: flat indexing over the chunk, 4 float4 per thread, loads batched
// (MLP=4). x reads are L2 hits (__ldcs: dead after use); out writes __stcs
// (evict-first, don't displace the next chunk). R2 shape, per-chunk range.
// 3,211,264 f4 / 1024 per block = 3136 blocks.
// ---------------------------------------------------------------------------
__global__ __launch_bounds__(256) void se_scale_chunk(
    const float* __restrict__ x,
    float* __restrict__ out,
    unsigned int base_f4)
{
    const unsigned int i = base_f4 + blockIdx.x * 1024u + threadIdx.x;

    const float4* __restrict__ x4 = reinterpret_cast<const float4*>(x);
    float4* __restrict__ o4       = reinterpret_cast<float4*>(out);

    float4 v[4];
    float  e[4];

    #pragma unroll
    for (int j = 0; j < 4; ++j)
        v[j] = __ldcs(x4 + (i + j * 256u));

    #pragma unroll
    for (int j = 0; j < 4; ++j)
        e[j] = __ldg(&d_e[(i + j * 256u) / 784u]);

    #pragma unroll
    for (int j = 0; j < 4; ++j) {
        float4 r = v[j];
        const float s = e[j];
        r.x *= s; r.y *= s; r.z *= s; r.w *= s;
        __stcs(o4 + (i + j * 256u), r);
    }
}

// ---------------------------------------------------------------------------
extern "C" void kernel_launch(void* const* d_in, const int* in_sizes, int n_in,
                              void* d_out, int out_size) {
    const float* x  = (const float*)d_in[0];
    const float* w1 = (const float*)d_in[1];
    const float* b1 = (const float*)d_in[2];
    const float* w2 = (const float*)d_in[3];
    const float* b2 = (const float*)d_in[4];
    float* out = (float*)d_out;

    for (int ck = 0; ck < NCHUNK; ++ck) {
        const int batch0 = ck * CHUNK_B;
        se_reduce_chunk<<<CHUNK_SLICES, 128>>>(x, batch0 * C);
        se_excite_chunk<<<CHUNK_B, 1024>>>(w1, b1, w2, b2, batch0);
        se_scale_chunk<<<CHUNK_F4 / 1024, 256>>>(x, out,
                                                 (unsigned int)(ck) * CHUNK_F4);
    }
}

// round 6
// speedup vs baseline: 2.1209x; 1.1573x over previous
#include <cuda_runtime.h>
#include <cstdint>

// x: [32, 512, 56, 56] fp32. Chunks of 8 batches (51.4 MB, L2-resident).
// Persistent kernel, 5 stages: stage s scales chunk s-1 (L2 read + DRAM write)
// while reducing chunk s (DRAM read). Mixed traffic keeps HBM at peak; total
// DRAM = 410 MB instead of 616 MB.

#define C            512
#define CR           32
#define SPATIAL4     784            // 56*56/4 float4 per slice
#define CHUNK_B      8
#define NCHUNK       4
#define CHUNK_SLICES 4096           // CHUNK_B * C

__device__ float d_sq[32 * C];

// --- generation-based grid barrier (grid is resident by construction) ------
__device__ unsigned int g_count = 0;
__device__ unsigned int g_gen   = 0;

__device__ __forceinline__ void grid_sync(unsigned int nblocks) {
    __syncthreads();
    if (threadIdx.x == 0) {
        __threadfence();
        unsigned int gen = atomicAdd(&g_gen, 0u);
        if (atomicAdd(&g_count, 1u) == nblocks - 1u) {
            atomicExch(&g_count, 0u);
            __threadfence();
            atomicAdd(&g_gen, 1u);
        } else {
            while (atomicAdd(&g_gen, 0u) == gen) { __nanosleep(64); }
        }
        __threadfence();
    }
    __syncthreads();
}

// ---------------------------------------------------------------------------
__global__ __launch_bounds__(256, 4) void se_pipe(
    const float* __restrict__ x,
    const float* __restrict__ w1,
    const float* __restrict__ b1,
    const float* __restrict__ w2,
    const float* __restrict__ b2,
    float* __restrict__ out,
    unsigned int nblocks)
{
    const int tid  = threadIdx.x;
    const int lane = tid & 31;
    const int wid  = tid >> 5;                 // 0..7

    const float4* __restrict__ x4 = reinterpret_cast<const float4*>(x);
    float4*       __restrict__ o4 = reinterpret_cast<float4*>(out);

    __shared__ float hid_s[CHUNK_B * CR];      // only [0 .. span*CR) used

    for (int s = 0; s < NCHUNK + 1; ++s) {
        const int sc = s - 1;                  // chunk being scaled
        const int rc = s;                      // chunk being reduced

        // per-block contiguous slice ranges within the chunk
        int s0 = 0, s1 = 0, r0 = 0, r1 = 0;
        if (sc >= 0) {
            s0 = (int)(((long long)blockIdx.x      * CHUNK_SLICES) / nblocks);
            s1 = (int)(((long long)(blockIdx.x+1)  * CHUNK_SLICES) / nblocks);
        }
        if (rc < NCHUNK) {
            r0 = (int)(((long long)blockIdx.x      * CHUNK_SLICES) / nblocks);
            r1 = (int)(((long long)(blockIdx.x+1)  * CHUNK_SLICES) / nblocks);
        }

        // ---- preamble: hidden units for the (<=2) batches this block scales
        int bl_lo = 0;
        if (sc >= 0 && s1 > s0) {
            bl_lo = s0 >> 9;
            const int bl_hi = (s1 - 1) >> 9;
            const int nh    = (bl_hi - bl_lo + 1) * CR;
            for (int h = wid; h < nh; h += 8) {
                const int bl = bl_lo + (h >> 5);
                const int j  = h & 31;
                const float* __restrict__ wrow = w1 + (size_t)j * C;
                const float* __restrict__ sqp  =
                    d_sq + (size_t)(sc * CHUNK_B + bl) * C;
                float acc = 0.0f;
                #pragma unroll
                for (int k = 0; k < 16; ++k) {
                    const int idx = lane + 32 * k;
                    acc = fmaf(__ldcg(&sqp[idx]), wrow[idx], acc);
                }
                #pragma unroll
                for (int off = 16; off > 0; off >>= 1)
                    acc += __shfl_down_sync(0xFFFFFFFFu, acc, off);
                if (lane == 0)
                    hid_s[h] = fmaxf(acc + __ldg(&b1[j]), 0.0f);
            }
        }
        __syncthreads();

        // ---- interleaved work loop: alternate scale / reduce slices -------
        int is = s0 + wid;
        int ir = r0 + wid;
        while (is < s1 || ir < r1) {
            if (is < s1) {                     // SCALE slice `is` of chunk sc
                const int bl = is >> 9;
                const int ch = is & (C - 1);
                const float* __restrict__ hb  = hid_s + (bl - bl_lo) * CR;
                const float* __restrict__ w2r = w2 + (size_t)ch * CR;
                float acc = __ldg(&b2[ch]);
                #pragma unroll
                for (int j = 0; j < CR; ++j)
                    acc = fmaf(hb[j], __ldg(&w2r[j]), acc);
                const float e = 1.0f / (1.0f + __expf(-acc));

                const size_t gs = (size_t)sc * CHUNK_SLICES + is;
                const float4* __restrict__ p = x4 + gs * SPATIAL4;
                float4*       __restrict__ q = o4 + gs * SPATIAL4;
                #pragma unroll
                for (int g = 0; g < 6; ++g) {
                    float4 v[4];
                    #pragma unroll
                    for (int i = 0; i < 4; ++i)
                        v[i] = __ldcs(p + lane + 32 * (g * 4 + i));
                    #pragma unroll
                    for (int i = 0; i < 4; ++i) {
                        float4 r = v[i];
                        r.x *= e; r.y *= e; r.z *= e; r.w *= e;
                        __stcs(q + lane + 32 * (g * 4 + i), r);
                    }
                }
                if (lane < 16) {
                    float4 v = __ldcs(p + 768 + lane);
                    v.x *= e; v.y *= e; v.z *= e; v.w *= e;
                    __stcs(q + 768 + lane, v);
                }
                is += 8;
            }
            if (ir < r1) {                     // REDUCE slice `ir` of chunk rc
                const size_t gs = (size_t)rc * CHUNK_SLICES + ir;
                const float4* __restrict__ p = x4 + gs * SPATIAL4;
                float acc = 0.0f;
                #pragma unroll
                for (int g = 0; g < 6; ++g) {
                    float4 v[4];
                    #pragma unroll
                    for (int i = 0; i < 4; ++i)
                        v[i] = p[lane + 32 * (g * 4 + i)];
                    #pragma unroll
                    for (int i = 0; i < 4; ++i)
                        acc += (v[i].x + v[i].y) + (v[i].z + v[i].w);
                }
                if (lane < 16) {
                    float4 v = p[768 + lane];
                    acc += (v.x + v.y) + (v.z + v.w);
                }
                #pragma unroll
                for (int off = 16; off > 0; off >>= 1)
                    acc += __shfl_down_sync(0xFFFFFFFFu, acc, off);
                if (lane == 0)
                    d_sq[gs] = acc * (1.0f / 3136.0f);
                ir += 8;
            }
        }

        if (s < NCHUNK) grid_sync(nblocks);
    }
}

// ---------------------------------------------------------------------------
extern "C" void kernel_launch(void* const* d_in, const int* in_sizes, int n_in,
                              void* d_out, int out_size) {
    const float* x  = (const float*)d_in[0];
    const float* w1 = (const float*)d_in[1];
    const float* b1 = (const float*)d_in[2];
    const float* w2 = (const float*)d_in[3];
    const float* b2 = (const float*)d_in[4];
    float* out = (float*)d_out;

    int dev = 0;
    cudaGetDevice(&dev);
    int nsm = 0;
    cudaDeviceGetAttribute(&nsm, cudaDevAttrMultiProcessorCount, dev);
    if (nsm <= 0) nsm = 148;

    const unsigned int nblocks = 4u * (unsigned int)nsm;
    se_pipe<<<nblocks, 256>>>(x, w1, b1, w2, b2, out, nblocks);
}